// round 8
// baseline (speedup 1.0000x reference)
#include <cuda_runtime.h>
#include <cuda_bf16.h>
#include <cstdint>

static constexpr int N   = 256;
static constexpr int B   = 512;
static constexpr int M   = N * (N - 1) / 2;  // 32640
static constexpr int TPB = 64;               // threads = batches per block
static constexpr int SS  = 36;               // smem row stride (floats): conflict-free .128
static constexpr long long NN = (long long)N * N;

__device__ __forceinline__ float sqrt_approx(float x) {
    float r;
    asm("sqrt.approx.f32 %0, %1;" : "=f"(r) : "f"(x));
    return r;
}

// One column step of the reference recurrence, reproducing its rounding:
//   t = 1 - rowsum ; x2 = (z*z) * t ; rowsum = rowsum + x2 ; out = sqrt(x2)*sign(z)
// __fadd_rn/__fmul_rn block FMA contraction so the fp32 sequence matches the
// reference's unfused mul/add (keeps the deep-column 1-rowsum plateau).
__device__ __forceinline__ float chol_step(float z, float& rowsum) {
    float t  = __fadd_rn(1.0f, -rowsum);
    float z2 = __fmul_rn(z, z);
    float x2 = __fmul_rn(z2, t);
    rowsum   = __fadd_rn(rowsum, x2);
    return copysignf(sqrt_approx(x2), z);
}

__device__ __forceinline__ uint32_t smem_u32(const void* p) {
    return (uint32_t)__cvta_generic_to_shared(p);
}

// 4-byte async copy with zero-fill: copies srcsz (0 or 4) bytes, zero-fills rest.
__device__ __forceinline__ void cp4(uint32_t dst, const float* src, int srcsz) {
    asm volatile("cp.async.ca.shared.global [%0], [%1], 4, %2;\n"
                 :: "r"(dst), "l"(src), "r"(srcsz));
}

__global__ void __launch_bounds__(TPB)
chol_from_z_kernel(const float* __restrict__ vec, float* __restrict__ out) {
    __shared__ float sA[TPB * SS];
    __shared__ float sB[TPB * SS];

    const int i    = (N - 1) - (int)blockIdx.x;      // longest rows first
    const int b0   = (int)blockIdx.y * TPB;
    const int tid  = (int)threadIdx.x;
    const int wrp  = tid >> 5;
    const int lane = tid & 31;

    const float* __restrict__ vrow = vec + (size_t)b0 * M + ((i * (i - 1)) >> 1);
    float* __restrict__ orow = out + ((size_t)b0 * N + i) * (size_t)N;

    const int ntiles = (i >> 5) + 1;   // 32-column tiles; last is mixed
    float* cur = sA;
    float* nxt = sB;

    // ---- prologue: async-load tile 0 (zfill past scan end) ----
    #pragma unroll
    for (int k = 0; k < 32; ++k) {
        int bb = 2 * k + wrp;                  // batch within block
        int ok = (lane < i);
        cp4(smem_u32(&cur[bb * SS + lane]),
            vrow + (size_t)bb * M + (ok ? lane : 0), ok ? 4 : 0);
    }
    asm volatile("cp.async.commit_group;\n");
    asm volatile("cp.async.wait_group 0;\n" ::: "memory");
    __syncthreads();

    float rowsum = 0.0f;
    for (int t = 0; t < ntiles; ++t) {
        const int j0 = t << 5;
        const bool more = (t + 1 < ntiles);

        // ---- prefetch tile t+1 straight into the other smem buffer ----
        if (more) {
            const int j1 = j0 + 32;
            #pragma unroll
            for (int k = 0; k < 32; ++k) {
                int bb = 2 * k + wrp;
                int j  = j1 + lane;
                int ok = (j < i);
                cp4(smem_u32(&nxt[bb * SS + lane]),
                    vrow + (size_t)bb * M + (ok ? j : 0), ok ? 4 : 0);
            }
            asm volatile("cp.async.commit_group;\n");
        }

        // ---- compute: thread = batch, serial chain over 32 columns ----
        float v[32];
        #pragma unroll
        for (int q = 0; q < 8; ++q) {          // LDS.128, conflict-free (stride 36)
            float4 f = *reinterpret_cast<const float4*>(&cur[tid * SS + 4 * q]);
            v[4 * q] = f.x; v[4 * q + 1] = f.y; v[4 * q + 2] = f.z; v[4 * q + 3] = f.w;
        }
        if (more) {                            // full tile: all columns < i
            #pragma unroll
            for (int jj = 0; jj < 32; ++jj) v[jj] = chol_step(v[jj], rowsum);
        } else {                               // mixed: last scan cols, diag 1, zeros
            #pragma unroll
            for (int jj = 0; jj < 32; ++jj) {
                int j = j0 + jj;               // uniform across block (same i)
                if (j < i)      v[jj] = chol_step(v[jj], rowsum);
                else            v[jj] = (j == i) ? 1.0f : 0.0f;
            }
        }
        #pragma unroll
        for (int q = 0; q < 8; ++q) {          // STS.128
            *reinterpret_cast<float4*>(&cur[tid * SS + 4 * q]) =
                make_float4(v[4 * q], v[4 * q + 1], v[4 * q + 2], v[4 * q + 3]);
        }
        __syncthreads();

        // ---- store tile t: coalesced STG.128 (128B per 8-lane group) ----
        #pragma unroll
        for (int it = 0; it < 8; ++it) {
            int flat = tid + TPB * it;         // lanes consecutive -> coalesced
            int bb = flat >> 3, q = flat & 7;
            float4 f = *reinterpret_cast<const float4*>(&cur[bb * SS + 4 * q]);
            *reinterpret_cast<float4*>(&orow[(size_t)bb * NN + j0 + 4 * q]) = f;
        }
        if (more) asm volatile("cp.async.wait_group 0;\n" ::: "memory");
        __syncthreads();
        float* tmp = cur; cur = nxt; nxt = tmp;
    }

    // ---- pure-zero region: columns [ntiles*32, N), coalesced float4 stores ----
    const int zstart = ntiles << 5;            // multiple of 32 -> 128B aligned
    const int nzq = (N - zstart) >> 2;
    if (nzq > 0) {
        const float4 z4 = make_float4(0.0f, 0.0f, 0.0f, 0.0f);
        for (int bb = wrp; bb < TPB; bb += 2) {
            float4* __restrict__ o4 =
                reinterpret_cast<float4*>(orow + (size_t)bb * NN + zstart);
            for (int q = lane; q < nzq; q += 32)
                o4[q] = z4;
        }
    }
}

extern "C" void kernel_launch(void* const* d_in, const int* in_sizes, int n_in,
                              void* d_out, int out_size) {
    const float* vec = (const float*)d_in[0];
    float* out = (float*)d_out;
    dim3 grid(N, B / TPB);  // (256, 8) -> 2048 blocks, 4096 warps
    chol_from_z_kernel<<<grid, TPB>>>(vec, out);
}